// round 2
// baseline (speedup 1.0000x reference)
#include <cuda_runtime.h>

#define NSAMP 8192
#define MAX_IN 8
#define IMG_DIM 3200
#define FC 512
#define NATTR 7
#define NANS 2
#define M1 (NSAMP * 3)

// ---------------- scratch (static device globals; no allocs) ----------------
__device__ __align__(16) float g_feats[M1 * FC];        // 50.3 MB  relu(img@Wcnn+b)
__device__ __align__(16) float g_x[NSAMP * 2 * FC];     // 33.5 MB  concat features
__device__ __align__(16) float g_h[NSAMP * FC];         // 16.8 MB  hidden layer
__device__ int g_counts[NATTR];
__device__ int g_offsets[NATTR];
__device__ int g_cursors[NATTR];
__device__ int g_idx[NSAMP];                            // sample ids sorted by attr

// ---------------- grouping: counting sort of samples by attr ----------------
__global__ void k_zero() {
    int t = threadIdx.x;
    if (t < NATTR) { g_counts[t] = 0; g_cursors[t] = 0; }
}
__global__ void k_count(const int* __restrict__ attrs) {
    int n = blockIdx.x * blockDim.x + threadIdx.x;
    if (n < NSAMP) atomicAdd(&g_counts[attrs[n]], 1);
}
__global__ void k_scan() {
    if (threadIdx.x == 0) {
        int o = 0;
        for (int a = 0; a < NATTR; a++) { g_offsets[a] = o; o += g_counts[a]; }
    }
}
__global__ void k_scatter(const int* __restrict__ attrs) {
    int n = blockIdx.x * blockDim.x + threadIdx.x;
    if (n < NSAMP) {
        int a = attrs[n];
        int p = atomicAdd(&g_cursors[a], 1);
        g_idx[g_offsets[a] + p] = n;
    }
}

// ---------------- GEMM1: feats = relu(img[:,0:3,:] @ Wcnn + b) --------------
// M=24576 (n,s) rows, K=3200, N=512. 128x128x16 tile, 256 thr, 8x8/thread.
#define BM1 128
#define BN1 128
#define BK1 16

__global__ __launch_bounds__(256) void k_gemm1(
    const float* __restrict__ img, const float* __restrict__ W,
    const float* __restrict__ bias)
{
    __shared__ __align__(16) float As[BK1][BM1];
    __shared__ __align__(16) float Bs[BK1][BN1];
    __shared__ const float* rowp[BM1];

    const int tid = threadIdx.x;
    const int bm0 = blockIdx.x * BM1;
    const int bn0 = blockIdx.y * BN1;

    if (tid < BM1) {
        int row = bm0 + tid;                 // row = n*3 + s
        int n = row / 3, s = row - 3 * n;
        rowp[tid] = img + (size_t)(n * MAX_IN + s) * IMG_DIM;
    }

    const int tm0 = (tid >> 4) << 3;         // 0..120 step 8 (M dir)
    const int tn0 = (tid & 15) << 3;         // 0..120 step 8 (N dir)

    // A-load mapping: 2 float4 per thread
    const int ar = tid >> 2;                 // rows ar and ar+64
    const int ak = (tid & 3) << 2;           // k offset 0,4,8,12
    // B-load mapping: 2 float4 per thread
    const int bk = tid >> 5;                 // k rows bk and bk+8
    const int bn4 = (tid & 31) << 2;         // col offset

    float acc[8][8];
#pragma unroll
    for (int i = 0; i < 8; i++)
#pragma unroll
        for (int j = 0; j < 8; j++) acc[i][j] = 0.f;

    for (int k0 = 0; k0 < IMG_DIM; k0 += BK1) {
        __syncthreads();   // protects rowp (iter 0) and smem reuse (iter>0)

        float4 a0 = *(const float4*)(rowp[ar] + k0 + ak);
        float4 a1 = *(const float4*)(rowp[ar + 64] + k0 + ak);
        As[ak + 0][ar] = a0.x; As[ak + 1][ar] = a0.y;
        As[ak + 2][ar] = a0.z; As[ak + 3][ar] = a0.w;
        As[ak + 0][ar + 64] = a1.x; As[ak + 1][ar + 64] = a1.y;
        As[ak + 2][ar + 64] = a1.z; As[ak + 3][ar + 64] = a1.w;

        *(float4*)&Bs[bk][bn4]     = *(const float4*)(W + (size_t)(k0 + bk) * FC + bn0 + bn4);
        *(float4*)&Bs[bk + 8][bn4] = *(const float4*)(W + (size_t)(k0 + bk + 8) * FC + bn0 + bn4);

        __syncthreads();

#pragma unroll
        for (int kk = 0; kk < BK1; kk++) {
            float4 av0 = *(const float4*)&As[kk][tm0];
            float4 av1 = *(const float4*)&As[kk][tm0 + 4];
            float4 bv0 = *(const float4*)&Bs[kk][tn0];
            float4 bv1 = *(const float4*)&Bs[kk][tn0 + 4];
            float a[8] = {av0.x, av0.y, av0.z, av0.w, av1.x, av1.y, av1.z, av1.w};
            float b[8] = {bv0.x, bv0.y, bv0.z, bv0.w, bv1.x, bv1.y, bv1.z, bv1.w};
#pragma unroll
            for (int i = 0; i < 8; i++)
#pragma unroll
                for (int j = 0; j < 8; j++)
                    acc[i][j] += a[i] * b[j];
        }
    }

    float bv[8];
    *(float4*)bv       = *(const float4*)(bias + bn0 + tn0);
    *(float4*)(bv + 4) = *(const float4*)(bias + bn0 + tn0 + 4);

#pragma unroll
    for (int i = 0; i < 8; i++) {
        int row = bm0 + tm0 + i;
        float4 o0, o1;
        o0.x = fmaxf(acc[i][0] + bv[0], 0.f);
        o0.y = fmaxf(acc[i][1] + bv[1], 0.f);
        o0.z = fmaxf(acc[i][2] + bv[2], 0.f);
        o0.w = fmaxf(acc[i][3] + bv[3], 0.f);
        o1.x = fmaxf(acc[i][4] + bv[4], 0.f);
        o1.y = fmaxf(acc[i][5] + bv[5], 0.f);
        o1.z = fmaxf(acc[i][6] + bv[6], 0.f);
        o1.w = fmaxf(acc[i][7] + bv[7], 0.f);
        *(float4*)(g_feats + (size_t)row * FC + bn0 + tn0)     = o0;
        *(float4*)(g_feats + (size_t)row * FC + bn0 + tn0 + 4) = o1;
    }
}

// ---------------- build x: concat(plain) or concat(products) ----------------
__global__ void k_makex(const int* __restrict__ attrs) {
    int i = blockIdx.x * blockDim.x + threadIdx.x;
    if (i >= NSAMP * FC) return;
    int n = i >> 9;            // /512
    int k = i & (FC - 1);
    int a = attrs[n];
    bool dist = (a >= 5);      // attrs in [0,7): 5 or 6
    float f0 = g_feats[(size_t)(n * 3 + 0) * FC + k];
    float f1 = g_feats[(size_t)(n * 3 + 1) * FC + k];
    float f2 = g_feats[(size_t)(n * 3 + 2) * FC + k];
    g_x[(size_t)n * (2 * FC) + k]      = dist ? f0 * f1 : f0;
    g_x[(size_t)n * (2 * FC) + FC + k] = dist ? f1 * f2 : f1;
}

// ---------------- GEMM2 (grouped by attr, gathered rows) --------------------
// Per block: 64 samples (one attr) x 128 outputs, K=1024. 256 thr, 8x4/thread.
#define BM2 64
#define BN2 128
#define BK2 16
#define CHUNKS ((NSAMP + BM2 - 1) / BM2)    // 128

__global__ __launch_bounds__(256) void k_gemm2(
    const float* __restrict__ W1, const float* __restrict__ b1)
{
    const int attr  = blockIdx.x / CHUNKS;
    const int chunk = blockIdx.x % CHUNKS;
    const int cnt   = g_counts[attr];
    if (chunk * BM2 >= cnt) return;
    const int base   = g_offsets[attr] + chunk * BM2;
    const int nvalid = min(BM2, cnt - chunk * BM2);

    __shared__ __align__(16) float As[BK2][BM2];
    __shared__ __align__(16) float Bs[BK2][BN2];
    __shared__ int sid[BM2];

    const int tid = threadIdx.x;
    const int bn0 = blockIdx.y * BN2;

    if (tid < BM2) sid[tid] = (tid < nvalid) ? g_idx[base + tid] : -1;
    __syncthreads();

    const float* Wp = W1 + (size_t)attr * (2 * FC) * FC;

    const int tm0 = (tid >> 5) << 3;      // sample dir: 0..56 step 8
    const int tn0 = (tid & 31) << 2;      // output dir: 0..124 step 4

    const int ar = tid >> 2;              // A row 0..63
    const int ak = (tid & 3) << 2;        // k offset 0,4,8,12
    const int bk = tid >> 5;              // B k rows bk, bk+8
    const int bn4 = (tid & 31) << 2;

    const int arow = sid[ar];             // gathered sample for A loads

    float acc[8][4];
#pragma unroll
    for (int i = 0; i < 8; i++)
#pragma unroll
        for (int j = 0; j < 4; j++) acc[i][j] = 0.f;

    for (int k0 = 0; k0 < 2 * FC; k0 += BK2) {
        __syncthreads();
        float4 av = make_float4(0.f, 0.f, 0.f, 0.f);
        if (arow >= 0)
            av = *(const float4*)(g_x + (size_t)arow * (2 * FC) + k0 + ak);
        As[ak + 0][ar] = av.x; As[ak + 1][ar] = av.y;
        As[ak + 2][ar] = av.z; As[ak + 3][ar] = av.w;

        *(float4*)&Bs[bk][bn4]     = *(const float4*)(Wp + (size_t)(k0 + bk) * FC + bn0 + bn4);
        *(float4*)&Bs[bk + 8][bn4] = *(const float4*)(Wp + (size_t)(k0 + bk + 8) * FC + bn0 + bn4);
        __syncthreads();

#pragma unroll
        for (int kk = 0; kk < BK2; kk++) {
            float4 av0 = *(const float4*)&As[kk][tm0];
            float4 av1 = *(const float4*)&As[kk][tm0 + 4];
            float4 bv0 = *(const float4*)&Bs[kk][tn0];
            float a[8] = {av0.x, av0.y, av0.z, av0.w, av1.x, av1.y, av1.z, av1.w};
            float b[4] = {bv0.x, bv0.y, bv0.z, bv0.w};
#pragma unroll
            for (int i = 0; i < 8; i++)
#pragma unroll
                for (int j = 0; j < 4; j++)
                    acc[i][j] += a[i] * b[j];
        }
    }

    float bv[4];
    *(float4*)bv = *(const float4*)(b1 + (size_t)attr * FC + bn0 + tn0);

#pragma unroll
    for (int i = 0; i < 8; i++) {
        int s = sid[tm0 + i];
        if (s < 0) continue;
        float4 o;
        o.x = fmaxf(acc[i][0] + bv[0], 0.f);
        o.y = fmaxf(acc[i][1] + bv[1], 0.f);
        o.z = fmaxf(acc[i][2] + bv[2], 0.f);
        o.w = fmaxf(acc[i][3] + bv[3], 0.f);
        *(float4*)(g_h + (size_t)s * FC + bn0 + tn0) = o;
    }
}

// ---------------- scores = h @ W2[attr] + b2 (warp per sample) --------------
__global__ __launch_bounds__(256) void k_out(
    const int* __restrict__ attrs, const float* __restrict__ W2,
    const float* __restrict__ b2, float* __restrict__ out)
{
    int warp = (blockIdx.x * blockDim.x + threadIdx.x) >> 5;
    int lane = threadIdx.x & 31;
    if (warp >= NSAMP) return;
    int n = warp;
    int a = attrs[n];
    const float* w = W2 + (size_t)a * FC * NANS;
    const float* hp = g_h + (size_t)n * FC;
    float s0 = 0.f, s1 = 0.f;
#pragma unroll
    for (int k = lane; k < FC; k += 32) {
        float hv = hp[k];
        s0 += hv * w[k * 2 + 0];
        s1 += hv * w[k * 2 + 1];
    }
#pragma unroll
    for (int o = 16; o; o >>= 1) {
        s0 += __shfl_down_sync(0xffffffffu, s0, o);
        s1 += __shfl_down_sync(0xffffffffu, s1, o);
    }
    if (lane == 0) {
        out[n * 2 + 0] = s0 + b2[a * 2 + 0];
        out[n * 2 + 1] = s1 + b2[a * 2 + 1];
    }
}

// ---------------- launch ----------------
extern "C" void kernel_launch(void* const* d_in, const int* in_sizes, int n_in,
                              void* d_out, int out_size) {
    const float* img   = (const float*)d_in[0];
    const int*   attrs = (const int*)d_in[1];
    const float* Wcnn  = (const float*)d_in[2];
    const float* bcnn  = (const float*)d_in[3];
    const float* W1    = (const float*)d_in[4];
    const float* b1    = (const float*)d_in[5];
    const float* W2    = (const float*)d_in[6];
    const float* b2    = (const float*)d_in[7];
    float* out = (float*)d_out;

    // group samples by attribute
    k_zero<<<1, 32>>>();
    k_count<<<(NSAMP + 255) / 256, 256>>>(attrs);
    k_scan<<<1, 32>>>();
    k_scatter<<<(NSAMP + 255) / 256, 256>>>(attrs);

    // layer 1: shared CNN projection + relu (dominant GEMM)
    dim3 g1(M1 / BM1, FC / BN1);
    k_gemm1<<<g1, 256>>>(img, Wcnn, bcnn);

    // build x (plain concat or product concat)
    k_makex<<<(NSAMP * FC + 255) / 256, 256>>>(attrs);

    // layer 2: grouped gathered GEMM + relu
    dim3 g2(NATTR * CHUNKS, FC / BN2);
    k_gemm2<<<g2, 256>>>(W1, b1);

    // layer 3: tiny per-sample output
    k_out<<<NSAMP / 8, 256>>>(attrs, W2, b2, out);
}

// round 3
// speedup vs baseline: 2.1616x; 2.1616x over previous
#include <cuda_runtime.h>
#include <cuda_bf16.h>
#include <stdint.h>

#define NSAMP 8192
#define MAX_IN 8
#define IMG_DIM 3200
#define FC 512
#define NATTR 7
#define NANS 2
#define M1 (NSAMP * 3)

// ---------------- scratch (static device globals; no allocs) ----------------
__device__ __align__(16) float g_feats[M1 * FC];        // relu(img@Wcnn+b)
__device__ __align__(16) float g_x[NSAMP * 2 * FC];     // concat features
__device__ __align__(16) float g_h[NSAMP * FC];         // hidden layer
__device__ int g_counts[NATTR];
__device__ int g_offsets[NATTR];
__device__ int g_cursors[NATTR];
__device__ int g_idx[NSAMP];                            // sample ids sorted by attr

// ---------------- grouping: counting sort of samples by attr ----------------
__global__ void k_zero() {
    int t = threadIdx.x;
    if (t < NATTR) { g_counts[t] = 0; g_cursors[t] = 0; }
}
__global__ void k_count(const int* __restrict__ attrs) {
    int n = blockIdx.x * blockDim.x + threadIdx.x;
    if (n < NSAMP) atomicAdd(&g_counts[attrs[n]], 1);
}
__global__ void k_scan() {
    if (threadIdx.x == 0) {
        int o = 0;
        for (int a = 0; a < NATTR; a++) { g_offsets[a] = o; o += g_counts[a]; }
    }
}
__global__ void k_scatter(const int* __restrict__ attrs) {
    int n = blockIdx.x * blockDim.x + threadIdx.x;
    if (n < NSAMP) {
        int a = attrs[n];
        int p = atomicAdd(&g_cursors[a], 1);
        g_idx[g_offsets[a] + p] = n;
    }
}

// ---------------- helpers: bf16 hi/lo split + mma ----------------
__device__ __forceinline__ uint32_t b2u(__nv_bfloat162 v) {
    return *reinterpret_cast<uint32_t*>(&v);
}

// split float4 into hi/lo bf16 and store 4 contiguous halves to each buffer
__device__ __forceinline__ void split4_store(float4 v,
                                             __nv_bfloat16* hp,
                                             __nv_bfloat16* lp) {
    __nv_bfloat162 h01, h23, l01, l23;
    h01.x = __float2bfloat16(v.x); h01.y = __float2bfloat16(v.y);
    h23.x = __float2bfloat16(v.z); h23.y = __float2bfloat16(v.w);
    l01.x = __float2bfloat16(v.x - __bfloat162float(h01.x));
    l01.y = __float2bfloat16(v.y - __bfloat162float(h01.y));
    l23.x = __float2bfloat16(v.z - __bfloat162float(h23.x));
    l23.y = __float2bfloat16(v.w - __bfloat162float(h23.y));
    *(__nv_bfloat162*)(hp)     = h01;
    *(__nv_bfloat162*)(hp + 2) = h23;
    *(__nv_bfloat162*)(lp)     = l01;
    *(__nv_bfloat162*)(lp + 2) = l23;
}

__device__ __forceinline__ void mma16816(float* c, const uint32_t* a, const uint32_t* b) {
    asm volatile(
        "mma.sync.aligned.m16n8k16.row.col.f32.bf16.bf16.f32 "
        "{%0,%1,%2,%3}, {%4,%5,%6,%7}, {%8,%9}, {%0,%1,%2,%3};\n"
        : "+f"(c[0]), "+f"(c[1]), "+f"(c[2]), "+f"(c[3])
        : "r"(a[0]), "r"(a[1]), "r"(a[2]), "r"(a[3]), "r"(b[0]), "r"(b[1]));
}

// ---------------- GEMM1 (tensor core): feats = relu(img[:,0:3,:]@Wcnn + b) --
// M=24576, K=3200, N=512. Block 128x128x32, 256 thr (8 warps), warp 64x32.
#define BM1 128
#define BN1 128
#define BK1 32
#define APAD 4
#define BPAD 8

__global__ __launch_bounds__(256) void k_gemm1_mma(
    const float* __restrict__ img, const float* __restrict__ W,
    const float* __restrict__ bias)
{
    __shared__ __align__(16) __nv_bfloat16 Ah[BM1][BK1 + APAD];
    __shared__ __align__(16) __nv_bfloat16 Al[BM1][BK1 + APAD];
    __shared__ __align__(16) __nv_bfloat16 Bh[BK1][BN1 + BPAD];
    __shared__ __align__(16) __nv_bfloat16 Bl[BK1][BN1 + BPAD];
    __shared__ const float* rowp[BM1];

    const int tid  = threadIdx.x;
    const int lane = tid & 31;
    const int warp = tid >> 5;
    const int bm0  = blockIdx.y * BM1;   // M tiles on y => N-strips co-scheduled
    const int bn0  = blockIdx.x * BN1;
    const int wm = (warp >> 2) * 64;
    const int wn = (warp & 3) * 32;
    const int fr = lane >> 2;            // 0..7
    const int fc = (lane & 3) * 2;       // 0,2,4,6

    if (tid < BM1) {
        int row = bm0 + tid;             // row = n*3 + s
        int n = row / 3, s = row - 3 * n;
        rowp[tid] = img + (size_t)(n * MAX_IN + s) * IMG_DIM;
    }
    __syncthreads();

    // gmem load mappings
    const int ar = tid >> 3;             // A rows ar + 32*rr
    const int ak = (tid & 7) * 4;        // k offset within tile
    const int bk = tid >> 5;             // B k-rows bk + 8*rr
    const int bc = lane * 4;             // B col offset

    const float* ap[4];
#pragma unroll
    for (int r = 0; r < 4; r++) ap[r] = rowp[ar + r * 32] + ak;
    const float* bp = W + (size_t)bk * FC + bn0 + bc;

    float acc[4][4][4];
#pragma unroll
    for (int mt = 0; mt < 4; mt++)
#pragma unroll
        for (int nt = 0; nt < 4; nt++)
#pragma unroll
            for (int i = 0; i < 4; i++) acc[mt][nt][i] = 0.f;

    float4 sa[4], sb[4];
#pragma unroll
    for (int r = 0; r < 4; r++) sa[r] = *(const float4*)(ap[r]);
#pragma unroll
    for (int r = 0; r < 4; r++) sb[r] = *(const float4*)(bp + (size_t)(r * 8) * FC);

    for (int k0 = 0; k0 < IMG_DIM; k0 += BK1) {
        // store staged tile (converted) to smem
#pragma unroll
        for (int r = 0; r < 4; r++)
            split4_store(sa[r], &Ah[ar + r * 32][ak], &Al[ar + r * 32][ak]);
#pragma unroll
        for (int r = 0; r < 4; r++)
            split4_store(sb[r], &Bh[bk + r * 8][bc], &Bl[bk + r * 8][bc]);
        __syncthreads();

        // prefetch next tile
        if (k0 + BK1 < IMG_DIM) {
#pragma unroll
            for (int r = 0; r < 4; r++)
                sa[r] = *(const float4*)(ap[r] + k0 + BK1);
#pragma unroll
            for (int r = 0; r < 4; r++)
                sb[r] = *(const float4*)(bp + (size_t)(k0 + BK1 + r * 8) * FC);
        }

#pragma unroll
        for (int ks = 0; ks < 2; ks++) {
            const int kb = ks * 16;
            uint32_t afh[4][4], afl[4][4], bfh[4][2], bfl[4][2];
#pragma unroll
            for (int mt = 0; mt < 4; mt++) {
                int r = wm + mt * 16 + fr;
                afh[mt][0] = *(const uint32_t*)&Ah[r][kb + fc];
                afh[mt][1] = *(const uint32_t*)&Ah[r + 8][kb + fc];
                afh[mt][2] = *(const uint32_t*)&Ah[r][kb + fc + 8];
                afh[mt][3] = *(const uint32_t*)&Ah[r + 8][kb + fc + 8];
                afl[mt][0] = *(const uint32_t*)&Al[r][kb + fc];
                afl[mt][1] = *(const uint32_t*)&Al[r + 8][kb + fc];
                afl[mt][2] = *(const uint32_t*)&Al[r][kb + fc + 8];
                afl[mt][3] = *(const uint32_t*)&Al[r + 8][kb + fc + 8];
            }
#pragma unroll
            for (int nt = 0; nt < 4; nt++) {
                int c = wn + nt * 8 + fr;
                __nv_bfloat162 t;
                t.x = Bh[kb + fc][c];     t.y = Bh[kb + fc + 1][c]; bfh[nt][0] = b2u(t);
                t.x = Bh[kb + fc + 8][c]; t.y = Bh[kb + fc + 9][c]; bfh[nt][1] = b2u(t);
                t.x = Bl[kb + fc][c];     t.y = Bl[kb + fc + 1][c]; bfl[nt][0] = b2u(t);
                t.x = Bl[kb + fc + 8][c]; t.y = Bl[kb + fc + 9][c]; bfl[nt][1] = b2u(t);
            }
#pragma unroll
            for (int mt = 0; mt < 4; mt++)
#pragma unroll
                for (int nt = 0; nt < 4; nt++) {
                    mma16816(acc[mt][nt], afh[mt], bfh[nt]);
                    mma16816(acc[mt][nt], afh[mt], bfl[nt]);
                    mma16816(acc[mt][nt], afl[mt], bfh[nt]);
                }
        }
        __syncthreads();
    }

    // epilogue: bias + relu -> g_feats
#pragma unroll
    for (int nt = 0; nt < 4; nt++) {
        int c = bn0 + wn + nt * 8 + fc;
        float b0 = bias[c], b1 = bias[c + 1];
#pragma unroll
        for (int mt = 0; mt < 4; mt++) {
            int r = bm0 + wm + mt * 16 + fr;
            float2 o;
            o.x = fmaxf(acc[mt][nt][0] + b0, 0.f);
            o.y = fmaxf(acc[mt][nt][1] + b1, 0.f);
            *(float2*)(g_feats + (size_t)r * FC + c) = o;
            o.x = fmaxf(acc[mt][nt][2] + b0, 0.f);
            o.y = fmaxf(acc[mt][nt][3] + b1, 0.f);
            *(float2*)(g_feats + (size_t)(r + 8) * FC + c) = o;
        }
    }
}

// ---------------- build x: concat(plain) or concat(products) ----------------
__global__ void k_makex(const int* __restrict__ attrs) {
    int i = blockIdx.x * blockDim.x + threadIdx.x;
    if (i >= NSAMP * FC) return;
    int n = i >> 9;
    int k = i & (FC - 1);
    int a = attrs[n];
    bool dist = (a >= 5);
    float f0 = g_feats[(size_t)(n * 3 + 0) * FC + k];
    float f1 = g_feats[(size_t)(n * 3 + 1) * FC + k];
    float f2 = g_feats[(size_t)(n * 3 + 2) * FC + k];
    g_x[(size_t)n * (2 * FC) + k]      = dist ? f0 * f1 : f0;
    g_x[(size_t)n * (2 * FC) + FC + k] = dist ? f1 * f2 : f1;
}

// ---------------- GEMM2 (tensor core, grouped by attr, gathered rows) -------
// Block: 64 samples x 128 outputs, K=1024. 256 thr, warp tile 32x32.
#define GM2 64
#define GN2 128
#define GK2 32
#define CHUNKS ((NSAMP + GM2 - 1) / GM2)    // 128

__global__ __launch_bounds__(256) void k_gemm2_mma(
    const float* __restrict__ W1, const float* __restrict__ b1)
{
    const int attr  = blockIdx.x / CHUNKS;
    const int chunk = blockIdx.x % CHUNKS;
    const int cnt   = g_counts[attr];
    if (chunk * GM2 >= cnt) return;
    const int base   = g_offsets[attr] + chunk * GM2;
    const int nvalid = min(GM2, cnt - chunk * GM2);

    __shared__ __align__(16) __nv_bfloat16 Ah[GM2][GK2 + APAD];
    __shared__ __align__(16) __nv_bfloat16 Al[GM2][GK2 + APAD];
    __shared__ __align__(16) __nv_bfloat16 Bh[GK2][GN2 + BPAD];
    __shared__ __align__(16) __nv_bfloat16 Bl[GK2][GN2 + BPAD];
    __shared__ int sid[GM2];

    const int tid  = threadIdx.x;
    const int lane = tid & 31;
    const int warp = tid >> 5;
    const int bn0  = blockIdx.y * GN2;
    const int wm = (warp >> 2) * 32;     // 0 or 32
    const int wn = (warp & 3) * 32;
    const int fr = lane >> 2;
    const int fc = (lane & 3) * 2;

    if (tid < GM2) sid[tid] = (tid < nvalid) ? g_idx[base + tid] : -1;
    __syncthreads();

    const float* Wp = W1 + (size_t)attr * (2 * FC) * FC;

    const int ar = tid >> 3;             // 0..31 : rows ar, ar+32
    const int ak = (tid & 7) * 4;
    const int bk = tid >> 5;
    const int bc = lane * 4;

    const int s0 = sid[ar];
    const int s1 = sid[ar + 32];
    const float* xp0 = g_x + (size_t)(s0 < 0 ? 0 : s0) * (2 * FC) + ak;
    const float* xp1 = g_x + (size_t)(s1 < 0 ? 0 : s1) * (2 * FC) + ak;
    const float* bp  = Wp + (size_t)bk * FC + bn0 + bc;

    float acc[2][4][4];
#pragma unroll
    for (int mt = 0; mt < 2; mt++)
#pragma unroll
        for (int nt = 0; nt < 4; nt++)
#pragma unroll
            for (int i = 0; i < 4; i++) acc[mt][nt][i] = 0.f;

    const float4 z4 = make_float4(0.f, 0.f, 0.f, 0.f);
    float4 sa0, sa1, sb[4];
    sa0 = (s0 >= 0) ? *(const float4*)(xp0) : z4;
    sa1 = (s1 >= 0) ? *(const float4*)(xp1) : z4;
#pragma unroll
    for (int r = 0; r < 4; r++) sb[r] = *(const float4*)(bp + (size_t)(r * 8) * FC);

    for (int k0 = 0; k0 < 2 * FC; k0 += GK2) {
        split4_store(sa0, &Ah[ar][ak],      &Al[ar][ak]);
        split4_store(sa1, &Ah[ar + 32][ak], &Al[ar + 32][ak]);
#pragma unroll
        for (int r = 0; r < 4; r++)
            split4_store(sb[r], &Bh[bk + r * 8][bc], &Bl[bk + r * 8][bc]);
        __syncthreads();

        if (k0 + GK2 < 2 * FC) {
            sa0 = (s0 >= 0) ? *(const float4*)(xp0 + k0 + GK2) : z4;
            sa1 = (s1 >= 0) ? *(const float4*)(xp1 + k0 + GK2) : z4;
#pragma unroll
            for (int r = 0; r < 4; r++)
                sb[r] = *(const float4*)(bp + (size_t)(k0 + GK2 + r * 8) * FC);
        }

#pragma unroll
        for (int ks = 0; ks < 2; ks++) {
            const int kb = ks * 16;
            uint32_t afh[2][4], afl[2][4], bfh[4][2], bfl[4][2];
#pragma unroll
            for (int mt = 0; mt < 2; mt++) {
                int r = wm + mt * 16 + fr;
                afh[mt][0] = *(const uint32_t*)&Ah[r][kb + fc];
                afh[mt][1] = *(const uint32_t*)&Ah[r + 8][kb + fc];
                afh[mt][2] = *(const uint32_t*)&Ah[r][kb + fc + 8];
                afh[mt][3] = *(const uint32_t*)&Ah[r + 8][kb + fc + 8];
                afl[mt][0] = *(const uint32_t*)&Al[r][kb + fc];
                afl[mt][1] = *(const uint32_t*)&Al[r + 8][kb + fc];
                afl[mt][2] = *(const uint32_t*)&Al[r][kb + fc + 8];
                afl[mt][3] = *(const uint32_t*)&Al[r + 8][kb + fc + 8];
            }
#pragma unroll
            for (int nt = 0; nt < 4; nt++) {
                int c = wn + nt * 8 + fr;
                __nv_bfloat162 t;
                t.x = Bh[kb + fc][c];     t.y = Bh[kb + fc + 1][c]; bfh[nt][0] = b2u(t);
                t.x = Bh[kb + fc + 8][c]; t.y = Bh[kb + fc + 9][c]; bfh[nt][1] = b2u(t);
                t.x = Bl[kb + fc][c];     t.y = Bl[kb + fc + 1][c]; bfl[nt][0] = b2u(t);
                t.x = Bl[kb + fc + 8][c]; t.y = Bl[kb + fc + 9][c]; bfl[nt][1] = b2u(t);
            }
#pragma unroll
            for (int mt = 0; mt < 2; mt++)
#pragma unroll
                for (int nt = 0; nt < 4; nt++) {
                    mma16816(acc[mt][nt], afh[mt], bfh[nt]);
                    mma16816(acc[mt][nt], afh[mt], bfl[nt]);
                    mma16816(acc[mt][nt], afl[mt], bfh[nt]);
                }
        }
        __syncthreads();
    }

    // epilogue: bias + relu -> g_h (gathered scatter back)
#pragma unroll
    for (int nt = 0; nt < 4; nt++) {
        int c = bn0 + wn + nt * 8 + fc;
        float b0 = b1[(size_t)attr * FC + c];
        float bb = b1[(size_t)attr * FC + c + 1];
#pragma unroll
        for (int mt = 0; mt < 2; mt++) {
            int r = wm + mt * 16 + fr;
            int sA = sid[r];
            int sB = sid[r + 8];
            if (sA >= 0) {
                float2 o;
                o.x = fmaxf(acc[mt][nt][0] + b0, 0.f);
                o.y = fmaxf(acc[mt][nt][1] + bb, 0.f);
                *(float2*)(g_h + (size_t)sA * FC + c) = o;
            }
            if (sB >= 0) {
                float2 o;
                o.x = fmaxf(acc[mt][nt][2] + b0, 0.f);
                o.y = fmaxf(acc[mt][nt][3] + bb, 0.f);
                *(float2*)(g_h + (size_t)sB * FC + c) = o;
            }
        }
    }
}

// ---------------- scores = h @ W2[attr] + b2 (warp per sample) --------------
__global__ __launch_bounds__(256) void k_out(
    const int* __restrict__ attrs, const float* __restrict__ W2,
    const float* __restrict__ b2, float* __restrict__ out)
{
    int warp = (blockIdx.x * blockDim.x + threadIdx.x) >> 5;
    int lane = threadIdx.x & 31;
    if (warp >= NSAMP) return;
    int n = warp;
    int a = attrs[n];
    const float* w = W2 + (size_t)a * FC * NANS;
    const float* hp = g_h + (size_t)n * FC;
    float s0 = 0.f, s1 = 0.f;
#pragma unroll
    for (int k = lane; k < FC; k += 32) {
        float hv = hp[k];
        s0 += hv * w[k * 2 + 0];
        s1 += hv * w[k * 2 + 1];
    }
#pragma unroll
    for (int o = 16; o; o >>= 1) {
        s0 += __shfl_down_sync(0xffffffffu, s0, o);
        s1 += __shfl_down_sync(0xffffffffu, s1, o);
    }
    if (lane == 0) {
        out[n * 2 + 0] = s0 + b2[a * 2 + 0];
        out[n * 2 + 1] = s1 + b2[a * 2 + 1];
    }
}

// ---------------- launch ----------------
extern "C" void kernel_launch(void* const* d_in, const int* in_sizes, int n_in,
                              void* d_out, int out_size) {
    const float* img   = (const float*)d_in[0];
    const int*   attrs = (const int*)d_in[1];
    const float* Wcnn  = (const float*)d_in[2];
    const float* bcnn  = (const float*)d_in[3];
    const float* W1    = (const float*)d_in[4];
    const float* b1    = (const float*)d_in[5];
    const float* W2    = (const float*)d_in[6];
    const float* b2    = (const float*)d_in[7];
    float* out = (float*)d_out;

    // group samples by attribute
    k_zero<<<1, 32>>>();
    k_count<<<(NSAMP + 255) / 256, 256>>>(attrs);
    k_scan<<<1, 32>>>();
    k_scatter<<<(NSAMP + 255) / 256, 256>>>(attrs);

    // layer 1: shared CNN projection + relu (dominant GEMM, tensor cores)
    dim3 g1(FC / BN1, M1 / BM1);     // x = N strips (4), y = M tiles (192)
    k_gemm1_mma<<<g1, 256>>>(img, Wcnn, bcnn);

    // build x (plain concat or product concat)
    k_makex<<<(NSAMP * FC + 255) / 256, 256>>>(attrs);

    // layer 2: grouped gathered GEMM + relu (tensor cores)
    dim3 g2(NATTR * CHUNKS, FC / GN2);
    k_gemm2_mma<<<g2, 256>>>(W1, b1);

    // layer 3: tiny per-sample output
    k_out<<<NSAMP / 8, 256>>>(attrs, W2, b2, out);
}